// round 15
// baseline (speedup 1.0000x reference)
#include <cuda_runtime.h>
#include <cuda_bf16.h>

#define SQL 2048
#define DMODEL 1024
#define NB 2
#define NH 16
#define HDIM 64

// Scratch (allocation-free rule: __device__ globals)
__device__ float g_qh [(size_t)NB * SQL * DMODEL];
__device__ float g_k  [(size_t)NB * SQL * DMODEL];
__device__ float g_v  [(size_t)NB * SQL * DMODEL];
__device__ float g_vt [(size_t)NB * NH * HDIM * SQL];   // V^T per head
__device__ float g_qc [(size_t)NB * SQL * DMODEL];      // tf32(q); later tf32(attn_out)
__device__ float g_kvc[(size_t)NB * SQL * DMODEL];      // tf32(kv)
__device__ float g_w  [(size_t)4 * DMODEL * DMODEL];    // tf32 W: [Wq | Wkv(2) | Wproj]

// ---------------------------------------------------------------------------
// tf32 / cp.async / ldmatrix helpers
// ---------------------------------------------------------------------------
__device__ __forceinline__ float f2tf32(float x) {
    unsigned u;
    asm("cvt.rna.tf32.f32 %0, %1;" : "=r"(u) : "f"(x));
    return __uint_as_float(u);
}

__device__ __forceinline__ void mma_tf32(
    float* c, const unsigned* a, const unsigned* b)
{
    asm volatile(
        "mma.sync.aligned.m16n8k8.row.col.f32.tf32.tf32.f32 "
        "{%0,%1,%2,%3}, {%4,%5,%6,%7}, {%8,%9}, {%0,%1,%2,%3};"
        : "+f"(c[0]), "+f"(c[1]), "+f"(c[2]), "+f"(c[3])
        : "r"(a[0]), "r"(a[1]), "r"(a[2]), "r"(a[3]),
          "r"(b[0]), "r"(b[1]));
}

__device__ __forceinline__ void ldsm4(
    unsigned& r0, unsigned& r1, unsigned& r2, unsigned& r3, unsigned addr)
{
    asm volatile(
        "ldmatrix.sync.aligned.m8n8.x4.shared.b16 {%0,%1,%2,%3}, [%4];"
        : "=r"(r0), "=r"(r1), "=r"(r2), "=r"(r3) : "r"(addr));
}

__device__ __forceinline__ void cp16(unsigned smem_dst, const void* gsrc) {
    asm volatile("cp.async.cg.shared.global [%0], [%1], 16;\n"
                 :: "r"(smem_dst), "l"(gsrc));
}
#define CP_COMMIT() asm volatile("cp.async.commit_group;\n" ::: "memory")
#define CP_WAIT(n)  asm volatile("cp.async.wait_group %0;\n" :: "n"(n) : "memory")

// ---------------------------------------------------------------------------
// Fused tf32 rounding pass over all 5 GEMM inputs (one launch).
// ---------------------------------------------------------------------------
#define NQ4  ((size_t)NB * SQL * DMODEL / 4)
#define NW4  ((size_t)DMODEL * DMODEL / 4)

__global__ __launch_bounds__(256) void cvt_all(
    const float4* __restrict__ q,  const float4* __restrict__ kv,
    const float4* __restrict__ wq, const float4* __restrict__ wkv,
    const float4* __restrict__ wp,
    float4* __restrict__ qc, float4* __restrict__ kvc,
    float4* __restrict__ w)
{
    size_t i = (size_t)blockIdx.x * 256 + threadIdx.x;
    const size_t A1 = NQ4, A2 = A1 + NQ4, A3 = A2 + NW4,
                 A4 = A3 + 2 * NW4, A5 = A4 + NW4;
    const float4* s;  float4* d;  size_t off;
    if      (i < A1) { s = q;   d = qc;            off = i; }
    else if (i < A2) { s = kv;  d = kvc;           off = i - A1; }
    else if (i < A3) { s = wq;  d = w;             off = i - A2; }
    else if (i < A4) { s = wkv; d = w + NW4;       off = i - A3; }
    else if (i < A5) { s = wp;  d = w + 3 * NW4;   off = i - A4; }
    else return;
    float4 v = s[off];
    d[off] = make_float4(f2tf32(v.x), f2tf32(v.y), f2tf32(v.z), f2tf32(v.w));
}

// ---------------------------------------------------------------------------
// tf32 GEMM body: 128x128 tile, 256 threads / 8 warps (64x32 warp-tile),
// 3-stage cp.async pipeline, ldmatrix A-fragments.  Shared by the fused
// QKV-projection kernel and the output-projection kernel.
// ---------------------------------------------------------------------------
#define GEMM_SMEM (3 * (128 * 20 + 16 * 136) * 4)   // 56832 B

__device__ __forceinline__ void gemm_body(
    const float* __restrict__ A, const float* __restrict__ Bm,
    float* __restrict__ C0, float* __restrict__ C1,
    int N, int halfN, int do_cvt, int bx, int by, float* gsm)
{
    const int K = DMODEL;
    float* sB_base = gsm + 3 * 128 * 20;

    const int t = threadIdx.x, lane = t & 31, warp = t >> 5;
    const int wm = warp >> 2, wn = warp & 3;
    const int brow = by * 128, bcol = bx * 128;

    float acc[4][4][4];
    #pragma unroll
    for (int mi = 0; mi < 4; mi++)
        #pragma unroll
        for (int ni = 0; ni < 4; ni++)
            #pragma unroll
            for (int r = 0; r < 4; r++) acc[mi][ni][r] = 0.0f;

    const int ar = t >> 2, asub = t & 3;
    const int bk = t >> 5, bsub = t & 31;
    const char* Ag0 = (const char*)(A + (size_t)(brow + ar) * K) + asub * 16;
    const char* Ag1 = Ag0 + (size_t)64 * K * 4;
    const char* Bg0 = (const char*)(Bm + (size_t)bk * N + bcol) + bsub * 16;
    const char* Bg1 = Bg0 + (size_t)8 * N * 4;

    unsigned sAa = (unsigned)__cvta_generic_to_shared(gsm);
    unsigned sBa = (unsigned)__cvta_generic_to_shared(sB_base);
    const unsigned Asm0 = sAa + (unsigned)(ar * 80 + asub * 16);
    const unsigned Asm1 = Asm0 + 64 * 80;
    const unsigned Bsm0 = sBa + (unsigned)(bk * 544 + bsub * 16);
    const unsigned Bsm1 = Bsm0 + 8 * 544;

    const int NIT = K / 16;

    #pragma unroll
    for (int s = 0; s < 2; s++) {
        cp16(Asm0 + s * 10240, Ag0 + s * 64);
        cp16(Asm1 + s * 10240, Ag1 + s * 64);
        cp16(Bsm0 + s * 8704, Bg0 + (size_t)s * 16 * N * 4);
        cp16(Bsm1 + s * 8704, Bg1 + (size_t)s * 16 * N * 4);
        CP_COMMIT();
    }

    const unsigned arow = (((lane >> 3) & 1) << 3) + (lane & 7);
    const unsigned akb  = (lane >> 4) << 2;

    for (int i = 0; i < NIT; i++) {
        if (i + 1 < NIT) { CP_WAIT(1); } else { CP_WAIT(0); }
        __syncthreads();
        if (i + 2 < NIT) {
            int s = (i + 2) % 3;
            cp16(Asm0 + s * 10240, Ag0 + (size_t)(i + 2) * 64);
            cp16(Asm1 + s * 10240, Ag1 + (size_t)(i + 2) * 64);
            cp16(Bsm0 + s * 8704, Bg0 + (size_t)(i + 2) * 16 * N * 4);
            cp16(Bsm1 + s * 8704, Bg1 + (size_t)(i + 2) * 16 * N * 4);
            CP_COMMIT();
        }
        const int st = i % 3;
        const unsigned abase = sAa + st * 10240;
        const float* bbuf = sB_base + st * (16 * 136);

        #pragma unroll
        for (int ks = 0; ks < 16; ks += 8) {
            unsigned af[4][4];
            #pragma unroll
            for (int mi = 0; mi < 4; mi++)
                ldsm4(af[mi][0], af[mi][1], af[mi][2], af[mi][3],
                      abase + ((wm * 64 + mi * 16 + arow) * 20 + ks + akb) * 4);
            unsigned bf[4][2];
            #pragma unroll
            for (int ni = 0; ni < 4; ni++) {
                int cb = wn * 32 + ni * 8 + (lane >> 2);
                int kr = ks + (lane & 3);
                bf[ni][0] = __float_as_uint(bbuf[kr * 136 + cb]);
                bf[ni][1] = __float_as_uint(bbuf[(kr + 4) * 136 + cb]);
            }
            #pragma unroll
            for (int mi = 0; mi < 4; mi++)
                #pragma unroll
                for (int ni = 0; ni < 4; ni++)
                    mma_tf32(acc[mi][ni], af[mi], bf[ni]);
        }
    }

    #pragma unroll
    for (int mi = 0; mi < 4; mi++) {
        #pragma unroll
        for (int ni = 0; ni < 4; ni++) {
            int row = brow + wm * 64 + mi * 16 + (lane >> 2);
            int col = bcol + wn * 32 + ni * 8 + 2 * (lane & 3);
            float* dst;
            int ccol = col;
            if (C1 && col >= halfN) { dst = C1; ccol = col - halfN; }
            else                    { dst = C0; }
            float v0 = acc[mi][ni][0], v1 = acc[mi][ni][1];
            float v2 = acc[mi][ni][2], v3 = acc[mi][ni][3];
            if (do_cvt) { v0 = f2tf32(v0); v1 = f2tf32(v1);
                          v2 = f2tf32(v2); v3 = f2tf32(v3); }
            *(float2*)(dst + (size_t)row * halfN + ccol) = make_float2(v0, v1);
            *(float2*)(dst + (size_t)(row + 8) * halfN + ccol) = make_float2(v2, v3);
        }
    }
}

// Fused Q-proj + KV-proj (independent GEMMs, one launch, 768 CTAs):
//   blockIdx.x <  8 : qh = qc @ Wq              (N=1024)
//   blockIdx.x >= 8 : [k|v] = kvc @ Wkv (split) (N=2048)
__global__ __launch_bounds__(256, 2) void gemm_qkv(
    const float* __restrict__ qc, const float* __restrict__ kvc,
    const float* __restrict__ w,
    float* __restrict__ qh, float* __restrict__ kb, float* __restrict__ vb)
{
    extern __shared__ float gsm[];
    int bx = blockIdx.x;
    if (bx < 8) {
        gemm_body(qc, w, qh, nullptr, DMODEL, DMODEL, 1, bx, blockIdx.y, gsm);
    } else {
        gemm_body(kvc, w + (size_t)DMODEL * DMODEL, kb, vb,
                  2 * DMODEL, DMODEL, 1, bx - 8, blockIdx.y, gsm);
    }
}

// Output projection: attn_proj = tf32(attn_out) @ Wproj
__global__ __launch_bounds__(256, 2) void gemm_proj(
    const float* __restrict__ A, const float* __restrict__ Bm,
    float* __restrict__ C0)
{
    extern __shared__ float gsm[];
    gemm_body(A, Bm, C0, nullptr, DMODEL, DMODEL, 0,
              blockIdx.x, blockIdx.y, gsm);
}

// ---------------------------------------------------------------------------
// LayerNorm (per-head, dim 64) + transpose to [b][h][d][skv]; tf32 output.
// ---------------------------------------------------------------------------
__global__ __launch_bounds__(256) void ln64t(
    const float* __restrict__ v, const float* __restrict__ gamma,
    const float* __restrict__ beta, float* __restrict__ vt)
{
    __shared__ float sT[64 * 68];

    int t = threadIdx.x, lane = t & 31, warp = t >> 5;
    int s0 = blockIdx.x * 64, h = blockIdx.y, b = blockIdx.z;

    float g0 = gamma[lane], g1 = gamma[lane + 32];
    float be0 = beta[lane], be1 = beta[lane + 32];

    #pragma unroll
    for (int i = 0; i < 8; i++) {
        int sl = warp * 8 + i;
        const float* p = v + ((size_t)(b * SQL + s0 + sl)) * DMODEL + h * HDIM;
        float x0 = p[lane], x1 = p[lane + 32];
        float s  = x0 + x1;
        float ss = x0 * x0 + x1 * x1;
        #pragma unroll
        for (int o = 16; o > 0; o >>= 1) {
            s  += __shfl_xor_sync(0xffffffffu, s,  o);
            ss += __shfl_xor_sync(0xffffffffu, ss, o);
        }
        float mu  = s * (1.0f / HDIM);
        float var = ss * (1.0f / HDIM) - mu * mu;
        float r   = rsqrtf(var + 1e-5f);
        sT[lane * 68 + sl]        = f2tf32((x0 - mu) * r * g0 + be0);
        sT[(lane + 32) * 68 + sl] = f2tf32((x1 - mu) * r * g1 + be1);
    }
    __syncthreads();

    int d = t >> 2, cg = (t & 3) * 16;
    float* ob = vt + ((size_t)(b * NH + h) * HDIM + d) * SQL + s0 + cg;
    #pragma unroll
    for (int i = 0; i < 4; i++)
        *(float4*)(ob + i * 4) = *(const float4*)&sT[d * 68 + cg + i * 4];
}

// ---------------------------------------------------------------------------
// Tensor-core flash sigmoid attention v5 (tf32 mma + ldmatrix).
// LPT scheduling: qb = 15 - blockIdx.x so the heaviest CTAs (most kv tiles)
// launch first; with 512 CTAs on ~296 slots this cuts the makespan tail.
// ---------------------------------------------------------------------------
__global__ __launch_bounds__(256, 2) void attn_tc(
    const float* __restrict__ qh, const float* __restrict__ kb,
    const float* __restrict__ vt, float* __restrict__ out,
    float* __restrict__ qc)
{
    extern __shared__ float sm[];
    float* sP = sm;                          // 128*68
    float* sK = sP + 128 * 68;               // 2*64*68
    float* sV = sK + 2 * 64 * 68;            // 2*64*68

    const int t = threadIdx.x, lane = t & 31, warp = t >> 5;
    const int qb = (int)gridDim.x - 1 - (int)blockIdx.x;   // big-first
    const int hd = blockIdx.y, b = blockIdx.z;
    const int q0 = qb * 128;

    const float* Qb  = qh + ((size_t)(b * SQL + q0)) * DMODEL + hd * HDIM;
    const float* Kb  = kb + ((size_t)b * SQL) * DMODEL + hd * HDIM;
    const float* Vtb = vt + ((size_t)(b * NH + hd) * HDIM) * SQL;

    unsigned sPa = (unsigned)__cvta_generic_to_shared(sP);
    unsigned sKa = (unsigned)__cvta_generic_to_shared(sK);
    unsigned sVa = (unsigned)__cvta_generic_to_shared(sV);

    // ---- stage Q ----
    {
        int r = t >> 1;
        int cgB = (t & 1) * 128;
        const char* src = (const char*)(Qb + (size_t)r * DMODEL) + cgB;
        unsigned dst = sPa + r * 272 + cgB;
        #pragma unroll
        for (int i = 0; i < 8; i++) cp16(dst + i * 16, src + i * 16);
    }
    CP_COMMIT();

    // ---- stage K / V^T tile 0 ----
    const int kr_ = t >> 2;
    const int kcB = (t & 3) * 64;
    {
        const char* ks = (const char*)(Kb + (size_t)kr_ * DMODEL) + kcB;
        const char* vs = (const char*)(Vtb + (size_t)kr_ * SQL) + kcB;
        unsigned kd = sKa + kr_ * 272 + kcB;
        unsigned vd = sVa + kr_ * 272 + kcB;
        #pragma unroll
        for (int i = 0; i < 4; i++) { cp16(kd + i * 16, ks + i * 16);
                                      cp16(vd + i * 16, vs + i * 16); }
    }
    CP_COMMIT();

    CP_WAIT(1);
    __syncwarp();

    const unsigned nb8   = (lane & 7) + ((lane >> 4) << 3);
    const unsigned kb4   = ((lane >> 3) & 1) << 2;
    const unsigned boffB = (nb8 * 68 + kb4) * 4;
    const unsigned arow  = (((lane >> 3) & 1) << 3) + (lane & 7);
    const unsigned akb   = (lane >> 4) << 2;
    const unsigned boffA = ((warp * 16 + arow) * 68 + akb) * 4;

    unsigned qf[8][4];
    #pragma unroll
    for (int kk = 0; kk < 8; kk++)
        ldsm4(qf[kk][0], qf[kk][1], qf[kk][2], qf[kk][3], sPa + boffA + kk * 32);
    __syncwarp();

    float oacc[8][4];
    #pragma unroll
    for (int ni = 0; ni < 8; ni++)
        #pragma unroll
        for (int r = 0; r < 4; r++) oacc[ni][r] = 0.0f;

    const int jmax = 2 * qb + 1;
    const int pr   = warp * 16 + (lane >> 2);
    const int qlim = q0 + warp * 16 + 15;

    for (int j = 0; j <= jmax; j++) {
        CP_WAIT(0);
        __syncthreads();
        if (j < jmax) {
            int k0n = (j + 1) * 64;
            const char* ks = (const char*)(Kb + (size_t)(k0n + kr_) * DMODEL) + kcB;
            const char* vs = (const char*)(Vtb + (size_t)kr_ * SQL + k0n) + kcB;
            unsigned kd = sKa + ((j + 1) & 1) * 17408 + kr_ * 272 + kcB;
            unsigned vd = sVa + ((j + 1) & 1) * 17408 + kr_ * 272 + kcB;
            #pragma unroll
            for (int i = 0; i < 4; i++) { cp16(kd + i * 16, ks + i * 16);
                                          cp16(vd + i * 16, vs + i * 16); }
            CP_COMMIT();
        }

        if (64 * j <= qlim) {
            unsigned kbase = sKa + (j & 1) * 17408;
            unsigned vbase = sVa + (j & 1) * 17408;

            #pragma unroll
            for (int half = 0; half < 2; half++) {
                float sfr[4][4];
                #pragma unroll
                for (int ni = 0; ni < 4; ni++)
                    #pragma unroll
                    for (int r = 0; r < 4; r++) sfr[ni][r] = 0.0f;
                #pragma unroll
                for (int kk = 0; kk < 8; kk++) {
                    #pragma unroll
                    for (int nip = 0; nip < 2; nip++) {
                        int np = half * 2 + nip;
                        unsigned b0, b1, b2, b3;
                        ldsm4(b0, b1, b2, b3,
                              kbase + np * 4352 + kk * 32 + boffB);
                        unsigned bl[2] = { b0, b1 }, bh[2] = { b2, b3 };
                        mma_tf32(sfr[nip * 2 + 0], qf[kk], bl);
                        mma_tf32(sfr[nip * 2 + 1], qf[kk], bh);
                    }
                }
                int g0 = q0 + pr, g1 = g0 + 8;
                #pragma unroll
                for (int n4 = 0; n4 < 4; n4++) {
                    int ni = half * 4 + n4;
                    int c  = ni * 8 + 2 * (lane & 3);
                    int gc = j * 64 + c;
                    float e0 = exp2f(fmaf(sfr[n4][0], -0.18033688f, 11.5415603f));
                    float e1 = exp2f(fmaf(sfr[n4][1], -0.18033688f, 11.5415603f));
                    float e2 = exp2f(fmaf(sfr[n4][2], -0.18033688f, 11.5415603f));
                    float e3 = exp2f(fmaf(sfr[n4][3], -0.18033688f, 11.5415603f));
                    float p00 = __fdividef(1.f, 1.f + e0);
                    float p01 = __fdividef(1.f, 1.f + e1);
                    float p10 = __fdividef(1.f, 1.f + e2);
                    float p11 = __fdividef(1.f, 1.f + e3);
                    p00 = (gc     <= g0) ? p00 : 0.f;
                    p01 = (gc + 1 <= g0) ? p01 : 0.f;
                    p10 = (gc     <= g1) ? p10 : 0.f;
                    p11 = (gc + 1 <= g1) ? p11 : 0.f;
                    *(float2*)&sP[pr * 68 + c] =
                        make_float2(f2tf32(p00), f2tf32(p01));
                    *(float2*)&sP[(pr + 8) * 68 + c] =
                        make_float2(f2tf32(p10), f2tf32(p11));
                }
            }
            __syncwarp();

            #pragma unroll
            for (int kk = 0; kk < 8; kk++) {
                unsigned pf[4];
                ldsm4(pf[0], pf[1], pf[2], pf[3], sPa + boffA + kk * 32);
                #pragma unroll
                for (int np = 0; np < 4; np++) {
                    unsigned b0, b1, b2, b3;
                    ldsm4(b0, b1, b2, b3,
                          vbase + np * 4352 + kk * 32 + boffB);
                    unsigned bl[2] = { b0, b1 }, bh[2] = { b2, b3 };
                    mma_tf32(oacc[np * 2 + 0], pf, bl);
                    mma_tf32(oacc[np * 2 + 1], pf, bh);
                }
            }
        }
    }

    // ---- epilogue: fp32 to out, tf32 twin to qc (feeds GEMM3) ----
    {
        size_t rowoff = ((size_t)(b * SQL + q0 + pr)) * DMODEL + hd * HDIM;
        float* ob = out + rowoff;
        float* pc = qc + rowoff;
        #pragma unroll
        for (int ni = 0; ni < 8; ni++) {
            int c = ni * 8 + 2 * (lane & 3);
            *(float2*)(ob + c) = make_float2(oacc[ni][0], oacc[ni][1]);
            *(float2*)(ob + (size_t)8 * DMODEL + c) =
                make_float2(oacc[ni][2], oacc[ni][3]);
            *(float2*)(pc + c) =
                make_float2(f2tf32(oacc[ni][0]), f2tf32(oacc[ni][1]));
            *(float2*)(pc + (size_t)8 * DMODEL + c) =
                make_float2(f2tf32(oacc[ni][2]), f2tf32(oacc[ni][3]));
        }
    }
}

#define ATTN_SMEM ((128 * 68 + 2 * 64 * 68 + 2 * 64 * 68) * 4)   // 104448 B

// ---------------------------------------------------------------------------
extern "C" void kernel_launch(void* const* d_in, const int* in_sizes, int n_in,
                              void* d_out, int out_size)
{
    const float* q     = (const float*)d_in[0];
    const float* kv    = (const float*)d_in[1];
    const float* Wq    = (const float*)d_in[2];
    const float* Wkv   = (const float*)d_in[3];
    const float* gamma = (const float*)d_in[4];
    const float* beta  = (const float*)d_in[5];
    const float* Wproj = (const float*)d_in[6];
    float* out = (float*)d_out;

    float *qh, *kbuf, *vbuf, *vtbuf, *qc, *kvc, *wbuf;
    cudaGetSymbolAddress((void**)&qh,    g_qh);
    cudaGetSymbolAddress((void**)&kbuf,  g_k);
    cudaGetSymbolAddress((void**)&vbuf,  g_v);
    cudaGetSymbolAddress((void**)&vtbuf, g_vt);
    cudaGetSymbolAddress((void**)&qc,    g_qc);
    cudaGetSymbolAddress((void**)&kvc,   g_kvc);
    cudaGetSymbolAddress((void**)&wbuf,  g_w);

    cudaFuncSetAttribute(attn_tc,
        cudaFuncAttributeMaxDynamicSharedMemorySize, ATTN_SMEM);
    cudaFuncSetAttribute(gemm_qkv,
        cudaFuncAttributeMaxDynamicSharedMemorySize, GEMM_SMEM);
    cudaFuncSetAttribute(gemm_proj,
        cudaFuncAttributeMaxDynamicSharedMemorySize, GEMM_SMEM);

    const int M  = NB * SQL;                 // 4096
    const size_t D2 = (size_t)DMODEL * DMODEL;

    // 0) fused tf32 pre-rounding of all GEMM inputs (one launch)
    {
        size_t total4 = 2 * NQ4 + 4 * NW4;
        cvt_all<<<(unsigned)((total4 + 255) / 256), 256>>>(
            (const float4*)q, (const float4*)kv,
            (const float4*)Wq, (const float4*)Wkv, (const float4*)Wproj,
            (float4*)qc, (float4*)kvc, (float4*)wbuf);
    }

    // 1+2) fused: qh = qc @ Wq ; [k|v] = kvc @ Wkv  (768 CTAs, one launch)
    gemm_qkv<<<dim3(24, M / 128), 256, GEMM_SMEM>>>(
        qc, kvc, wbuf, qh, kbuf, vbuf);

    // 3) per-head LayerNorm of V + transpose into g_vt (tf32)
    ln64t<<<dim3(SQL / 64, NH, NB), 256>>>(vbuf, gamma, beta, vtbuf);

    // 4) attention -> attn_times_v (fp32 to out) + tf32 twin into qc
    attn_tc<<<dim3(SQL / 128, NH, NB), 256, ATTN_SMEM>>>(
        qh, kbuf, vtbuf, out, qc);

    // 5) attn_proj = tf32(attn_times_v) @ Wproj (fp32 out)
    gemm_proj<<<dim3(DMODEL / 128, M / 128), 256, GEMM_SMEM>>>(
        qc, wbuf + 3 * D2, out + (size_t)M * DMODEL);
}